// round 11
// baseline (speedup 1.0000x reference)
#include <cuda_runtime.h>
#include <cuda_bf16.h>

// CopyMechanism fused kernel (pointer-generator): gate + vocab scale + scatter.
// B=16, T=128, H=512, V=32000, S=400.
//
// R5: eighth-row tiling (16384 CTAs, ~13.8 waves) — finer wave smoothing than
// R4's quarter tiles — plus single-barrier gate reduction. Scatter remains
// range-filtered per tile (each CTA atomics only into the region it wrote,
// so __syncthreads is sufficient ordering). Gate recomputed per tile; the
// redundant reads are L2 hits (zero extra DRAM).
//
// Inputs (metadata order):
//  0 context_vecs [B,T,H] f32,  1 hidden [B,T,H] f32,  2 trg_embs [B,T,H] f32
//  3 vocab_dists [B,T,V] f32,   4 attn_dists [B,T,S] f32, 5 src_ids [B,T,S] i32
//  6 pad_id (unused), 7 w_h [1,H], 8 w_s [1,H], 9 w_x_w [1,H], 10 w_x_b [1]
// output: [B,T,V] f32

#define HDIM 512
#define VDIM 32000
#define SDIM 400
#define NTHREADS 256
#define NWARPS (NTHREADS / 32)
#define TILES_PER_ROW 8
#define TILE_ELEMS (VDIM / TILES_PER_ROW)   // 4000 floats
#define TILE4 (TILE_ELEMS / 4)              // 1000 float4

__global__ __launch_bounds__(NTHREADS)
void copy_mechanism_kernel(
    const float* __restrict__ ctx,
    const float* __restrict__ hid,
    const float* __restrict__ trg,
    const float* __restrict__ vocab,
    const float* __restrict__ attn,
    const int*   __restrict__ src_ids,
    const float* __restrict__ w_h,
    const float* __restrict__ w_s,
    const float* __restrict__ w_x,
    const float* __restrict__ w_b,
    float* __restrict__ out)
{
    const int row  = blockIdx.x >> 3;       // 0 .. B*T-1
    const int tile = blockIdx.x & 7;        // which eighth of the row
    const int tid  = threadIdx.x;
    const int lane = tid & 31;
    const int warp = tid >> 5;

    __shared__ float s_red[NWARPS];

    // ---- Phase 1: gate logit = <ctx,w_h> + <hid,w_s> + <trg,w_x> + b ----
    // Redundant across the 8 tiles of a row; lines are L2-hot.
    {
        const float2* c2  = reinterpret_cast<const float2*>(ctx + (size_t)row * HDIM);
        const float2* h2  = reinterpret_cast<const float2*>(hid + (size_t)row * HDIM);
        const float2* t2  = reinterpret_cast<const float2*>(trg + (size_t)row * HDIM);
        const float2* wh2 = reinterpret_cast<const float2*>(w_h);
        const float2* ws2 = reinterpret_cast<const float2*>(w_s);
        const float2* wx2 = reinterpret_cast<const float2*>(w_x);

        // HDIM/2 = 256 float2 -> exactly one per thread
        float2 cv = c2[tid], hv = h2[tid], tv = t2[tid];
        float2 wh = wh2[tid], ws = ws2[tid], wx = wx2[tid];
        float acc = cv.x * wh.x + cv.y * wh.y
                  + hv.x * ws.x + hv.y * ws.y
                  + tv.x * wx.x + tv.y * wx.y;

        #pragma unroll
        for (int o = 16; o > 0; o >>= 1)
            acc += __shfl_down_sync(0xFFFFFFFFu, acc, o);
        if (lane == 0) s_red[warp] = acc;
    }
    const float bias = w_b[0];
    __syncthreads();   // single barrier: warp partials visible

    // Redundant final combine in every thread (no broadcast barrier needed).
    float logit = bias;
    #pragma unroll
    for (int w = 0; w < NWARPS; w++) logit += s_red[w];
    const float p_gen     = 1.0f / (1.0f + __expf(-logit));
    const float one_minus = 1.0f - p_gen;

    // ---- Phase 2: out = p_gen * vocab over this tile (float4 stream) ----
    {
        const float4* v4 = reinterpret_cast<const float4*>(vocab + (size_t)row * VDIM)
                         + tile * TILE4;
        float4* o4 = reinterpret_cast<float4*>(out + (size_t)row * VDIM)
                   + tile * TILE4;
        #pragma unroll 4
        for (int i = tid; i < TILE4; i += NTHREADS) {
            float4 v = v4[i];
            v.x *= p_gen; v.y *= p_gen; v.z *= p_gen; v.w *= p_gen;
            o4[i] = v;
        }
    }

    __syncthreads();   // tile fully written before scatter RMW into it

    // ---- Phase 3: range-filtered scatter-add into THIS tile only ----
    {
        const int lo = tile * TILE_ELEMS;
        const int hi = lo + TILE_ELEMS;
        const float* a   = attn + (size_t)row * SDIM;
        const int*   ids = src_ids + (size_t)row * SDIM;
        float* orow = out + (size_t)row * VDIM;
        for (int j = tid; j < SDIM; j += NTHREADS) {
            int id = ids[j];
            if (id >= lo && id < hi)
                atomicAdd(&orow[id], one_minus * a[j]);
        }
    }
}

extern "C" void kernel_launch(void* const* d_in, const int* in_sizes, int n_in,
                              void* d_out, int out_size) {
    const float* ctx   = (const float*)d_in[0];
    const float* hid   = (const float*)d_in[1];
    const float* trg   = (const float*)d_in[2];
    const float* vocab = (const float*)d_in[3];
    const float* attn  = (const float*)d_in[4];
    const int*   sid   = (const int*)d_in[5];
    const float* w_h   = (const float*)d_in[7];
    const float* w_s   = (const float*)d_in[8];
    const float* w_x   = (const float*)d_in[9];
    const float* w_b   = (const float*)d_in[10];
    float* out = (float*)d_out;

    const int rows = in_sizes[0] / HDIM;  // B*T = 2048
    copy_mechanism_kernel<<<rows * TILES_PER_ROW, NTHREADS>>>(
        ctx, hid, trg, vocab, attn, sid, w_h, w_s, w_x, w_b, out);
}

// round 12
// speedup vs baseline: 1.2052x; 1.2052x over previous
#include <cuda_runtime.h>
#include <cuda_bf16.h>

// CopyMechanism (pointer-generator): gate + vocab scale + scatter.
// B=16, T=128, H=512, V=32000, S=400.
//
// R6: two kernels.
//  K1 (gate): one CTA per row (2048 CTAs, 128 thr), p_gen -> __device__ scratch.
//  K2 (stream+scatter): R4's proven quarter-tile layout (8192 CTAs), but gate
//     phase replaced by a single scratch load. Scatter stays range-filtered
//     per tile (CTA only atomics into the quarter it wrote; __syncthreads
//     is sufficient ordering). Plain loads/stores, direct indexing.
//
// Inputs (metadata order):
//  0 context_vecs [B,T,H] f32,  1 hidden [B,T,H] f32,  2 trg_embs [B,T,H] f32
//  3 vocab_dists [B,T,V] f32,   4 attn_dists [B,T,S] f32, 5 src_ids [B,T,S] i32
//  6 pad_id (unused), 7 w_h [1,H], 8 w_s [1,H], 9 w_x_w [1,H], 10 w_x_b [1]
// output: [B,T,V] f32

#define HDIM 512
#define VDIM 32000
#define SDIM 400
#define NROWS 2048
#define NTHREADS 256
#define TILES_PER_ROW 4
#define TILE_ELEMS (VDIM / TILES_PER_ROW)   // 8000 floats
#define TILE4 (TILE_ELEMS / 4)              // 2000 float4

__device__ float g_pgen[NROWS];

// ---------------- K1: gate -> p_gen ----------------
// One CTA per row, 128 threads; each thread handles one float4 (H/4/128 = 1).
__global__ __launch_bounds__(128)
void gate_kernel(const float* __restrict__ ctx,
                 const float* __restrict__ hid,
                 const float* __restrict__ trg,
                 const float* __restrict__ w_h,
                 const float* __restrict__ w_s,
                 const float* __restrict__ w_x,
                 const float* __restrict__ w_b)
{
    const int row  = blockIdx.x;
    const int tid  = threadIdx.x;
    const int lane = tid & 31;
    const int warp = tid >> 5;

    __shared__ float s_red[4];

    const float4* c4  = reinterpret_cast<const float4*>(ctx + (size_t)row * HDIM);
    const float4* h4  = reinterpret_cast<const float4*>(hid + (size_t)row * HDIM);
    const float4* t4  = reinterpret_cast<const float4*>(trg + (size_t)row * HDIM);
    const float4* wh4 = reinterpret_cast<const float4*>(w_h);
    const float4* ws4 = reinterpret_cast<const float4*>(w_s);
    const float4* wx4 = reinterpret_cast<const float4*>(w_x);

    // HDIM/4 = 128 float4 -> exactly one per thread
    float4 c = c4[tid], h = h4[tid], t = t4[tid];
    float4 a = wh4[tid], b = ws4[tid], x = wx4[tid];
    float acc = c.x * a.x + c.y * a.y + c.z * a.z + c.w * a.w
              + h.x * b.x + h.y * b.y + h.z * b.z + h.w * b.w
              + t.x * x.x + t.y * x.y + t.z * x.z + t.w * x.w;

    #pragma unroll
    for (int o = 16; o > 0; o >>= 1)
        acc += __shfl_down_sync(0xFFFFFFFFu, acc, o);
    if (lane == 0) s_red[warp] = acc;
    __syncthreads();
    if (tid == 0) {
        float logit = s_red[0] + s_red[1] + s_red[2] + s_red[3] + w_b[0];
        g_pgen[row] = 1.0f / (1.0f + __expf(-logit));
    }
}

// ---------------- K2: streaming scale + range-filtered scatter ----------------
__global__ __launch_bounds__(NTHREADS)
void scale_scatter_kernel(const float* __restrict__ vocab,
                          const float* __restrict__ attn,
                          const int*   __restrict__ src_ids,
                          float* __restrict__ out)
{
    const int row  = blockIdx.x >> 2;       // 0 .. NROWS-1
    const int tile = blockIdx.x & 3;        // which quarter of the row
    const int tid  = threadIdx.x;

    const float p_gen     = __ldg(&g_pgen[row]);   // L1/L2-hot, 8 KB total
    const float one_minus = 1.0f - p_gen;

    // ---- streaming scale over this quarter ----
    {
        const float4* v4 = reinterpret_cast<const float4*>(vocab + (size_t)row * VDIM)
                         + tile * TILE4;
        float4* o4 = reinterpret_cast<float4*>(out + (size_t)row * VDIM)
                   + tile * TILE4;
        #pragma unroll 4
        for (int i = tid; i < TILE4; i += NTHREADS) {
            float4 v = v4[i];
            v.x *= p_gen; v.y *= p_gen; v.z *= p_gen; v.w *= p_gen;
            o4[i] = v;
        }
    }

    __syncthreads();   // tile fully written before scatter RMW into it

    // ---- range-filtered scatter-add into THIS tile only ----
    {
        const int lo = tile * TILE_ELEMS;
        const int hi = lo + TILE_ELEMS;
        const float* a   = attn + (size_t)row * SDIM;
        const int*   ids = src_ids + (size_t)row * SDIM;
        float* orow = out + (size_t)row * VDIM;
        for (int j = tid; j < SDIM; j += NTHREADS) {
            int id = ids[j];
            if (id >= lo && id < hi)
                atomicAdd(&orow[id], one_minus * a[j]);
        }
    }
}

extern "C" void kernel_launch(void* const* d_in, const int* in_sizes, int n_in,
                              void* d_out, int out_size) {
    const float* ctx   = (const float*)d_in[0];
    const float* hid   = (const float*)d_in[1];
    const float* trg   = (const float*)d_in[2];
    const float* vocab = (const float*)d_in[3];
    const float* attn  = (const float*)d_in[4];
    const int*   sid   = (const int*)d_in[5];
    const float* w_h   = (const float*)d_in[7];
    const float* w_s   = (const float*)d_in[8];
    const float* w_x   = (const float*)d_in[9];
    const float* w_b   = (const float*)d_in[10];
    float* out = (float*)d_out;

    gate_kernel<<<NROWS, 128>>>(ctx, hid, trg, w_h, w_s, w_x, w_b);
    scale_scatter_kernel<<<NROWS * TILES_PER_ROW, NTHREADS>>>(vocab, attn, sid, out);
}

// round 15
// speedup vs baseline: 1.2069x; 1.0014x over previous
#include <cuda_runtime.h>
#include <cuda_bf16.h>

// CopyMechanism (pointer-generator): gate + vocab scale + scatter.
// B=16, T=128, H=512, V=32000, S=400.
//
// R8 (= R7 retry): two-kernel split + Programmatic Dependent Launch overlap.
//  K1 (gate): one CTA per row (2048 CTAs, 128 thr) -> g_pgen scratch.
//     Triggers programmatic launch completion at entry.
//  K2 (stream+scatter): quarter-tile layout (8192 CTAs), proven 82.7us body.
//     cudaGridDependencySynchronize() before reading g_pgen.
//
// Inputs (metadata order):
//  0 context_vecs [B,T,H] f32,  1 hidden [B,T,H] f32,  2 trg_embs [B,T,H] f32
//  3 vocab_dists [B,T,V] f32,   4 attn_dists [B,T,S] f32, 5 src_ids [B,T,S] i32
//  6 pad_id (unused), 7 w_h [1,H], 8 w_s [1,H], 9 w_x_w [1,H], 10 w_x_b [1]
// output: [B,T,V] f32

#define HDIM 512
#define VDIM 32000
#define SDIM 400
#define NROWS 2048
#define NTHREADS 256
#define TILES_PER_ROW 4
#define TILE_ELEMS (VDIM / TILES_PER_ROW)   // 8000 floats
#define TILE4 (TILE_ELEMS / 4)              // 2000 float4

__device__ float g_pgen[NROWS];

// ---------------- K1: gate -> p_gen ----------------
__global__ __launch_bounds__(128)
void gate_kernel(const float* __restrict__ ctx,
                 const float* __restrict__ hid,
                 const float* __restrict__ trg,
                 const float* __restrict__ w_h,
                 const float* __restrict__ w_s,
                 const float* __restrict__ w_x,
                 const float* __restrict__ w_b)
{
    // Let the dependent kernel (K2) begin scheduling immediately; K2's
    // cudaGridDependencySynchronize still waits for this grid to finish.
    cudaTriggerProgrammaticLaunchCompletion();

    const int row  = blockIdx.x;
    const int tid  = threadIdx.x;
    const int lane = tid & 31;
    const int warp = tid >> 5;

    __shared__ float s_red[4];

    const float4* c4  = reinterpret_cast<const float4*>(ctx + (size_t)row * HDIM);
    const float4* h4  = reinterpret_cast<const float4*>(hid + (size_t)row * HDIM);
    const float4* t4  = reinterpret_cast<const float4*>(trg + (size_t)row * HDIM);
    const float4* wh4 = reinterpret_cast<const float4*>(w_h);
    const float4* ws4 = reinterpret_cast<const float4*>(w_s);
    const float4* wx4 = reinterpret_cast<const float4*>(w_x);

    // HDIM/4 = 128 float4 -> exactly one per thread
    float4 c = c4[tid], h = h4[tid], t = t4[tid];
    float4 a = wh4[tid], b = ws4[tid], x = wx4[tid];
    float acc = c.x * a.x + c.y * a.y + c.z * a.z + c.w * a.w
              + h.x * b.x + h.y * b.y + h.z * b.z + h.w * b.w
              + t.x * x.x + t.y * x.y + t.z * x.z + t.w * x.w;

    #pragma unroll
    for (int o = 16; o > 0; o >>= 1)
        acc += __shfl_down_sync(0xFFFFFFFFu, acc, o);
    if (lane == 0) s_red[warp] = acc;
    __syncthreads();
    if (tid == 0) {
        float logit = s_red[0] + s_red[1] + s_red[2] + s_red[3] + w_b[0];
        g_pgen[row] = 1.0f / (1.0f + __expf(-logit));
    }
}

// ---------------- K2: streaming scale + range-filtered scatter ----------------
__global__ __launch_bounds__(NTHREADS)
void scale_scatter_kernel(const float* __restrict__ vocab,
                          const float* __restrict__ attn,
                          const int*   __restrict__ src_ids,
                          float* __restrict__ out)
{
    const int row  = blockIdx.x >> 2;       // 0 .. NROWS-1
    const int tile = blockIdx.x & 3;        // which quarter of the row
    const int tid  = threadIdx.x;

    // Address setup only (no K1-dependent data touched yet).
    const float4* v4 = reinterpret_cast<const float4*>(vocab + (size_t)row * VDIM)
                     + tile * TILE4;
    float4* o4 = reinterpret_cast<float4*>(out + (size_t)row * VDIM)
               + tile * TILE4;

    // Wait for gate_kernel's writes to be visible (PDL dependency).
    cudaGridDependencySynchronize();

    const float p_gen     = __ldg(&g_pgen[row]);   // L1/L2-hot, 8 KB total
    const float one_minus = 1.0f - p_gen;

    // ---- streaming scale over this quarter ----
    #pragma unroll 4
    for (int i = tid; i < TILE4; i += NTHREADS) {
        float4 v = v4[i];
        v.x *= p_gen; v.y *= p_gen; v.z *= p_gen; v.w *= p_gen;
        o4[i] = v;
    }

    __syncthreads();   // tile fully written before scatter RMW into it

    // ---- range-filtered scatter-add into THIS tile only ----
    {
        const int lo = tile * TILE_ELEMS;
        const int hi = lo + TILE_ELEMS;
        const float* a   = attn + (size_t)row * SDIM;
        const int*   ids = src_ids + (size_t)row * SDIM;
        float* orow = out + (size_t)row * VDIM;
        for (int j = tid; j < SDIM; j += NTHREADS) {
            int id = ids[j];
            if (id >= lo && id < hi)
                atomicAdd(&orow[id], one_minus * a[j]);
        }
    }
}

extern "C" void kernel_launch(void* const* d_in, const int* in_sizes, int n_in,
                              void* d_out, int out_size) {
    const float* ctx   = (const float*)d_in[0];
    const float* hid   = (const float*)d_in[1];
    const float* trg   = (const float*)d_in[2];
    const float* vocab = (const float*)d_in[3];
    const float* attn  = (const float*)d_in[4];
    const int*   sid   = (const int*)d_in[5];
    const float* w_h   = (const float*)d_in[7];
    const float* w_s   = (const float*)d_in[8];
    const float* w_x   = (const float*)d_in[9];
    const float* w_b   = (const float*)d_in[10];
    float* out = (float*)d_out;

    // K1: plain launch on the capture (legacy) stream.
    gate_kernel<<<NROWS, 128>>>(ctx, hid, trg, w_h, w_s, w_x, w_b);

    // K2: Programmatic Stream Serialization — may begin scheduling while K1
    // drains; synchronizes in-kernel before consuming K1's output.
    {
        cudaLaunchConfig_t cfg = {};
        cfg.gridDim  = dim3(NROWS * TILES_PER_ROW);
        cfg.blockDim = dim3(NTHREADS);
        cfg.dynamicSmemBytes = 0;
        cfg.stream = 0;   // same (legacy) stream the harness captures

        cudaLaunchAttribute attrs[1];
        attrs[0].id = cudaLaunchAttributeProgrammaticStreamSerialization;
        attrs[0].val.programmaticStreamSerializationAllowed = 1;
        cfg.attrs = attrs;
        cfg.numAttrs = 1;

        cudaLaunchKernelEx(&cfg, scale_scatter_kernel, vocab, attn, sid, out);
    }
}